// round 2
// baseline (speedup 1.0000x reference)
#include <cuda_runtime.h>

#define H 512
#define W 512
#define CS 21          // src channels
#define CI 3           // im channels
#define RH 128
#define RW 128
#define RAD 12
#define SRCP 24        // padded channels (6 x float4)
#define IMP 4          // im padded channels

// Scratch in device globals (no allocation allowed).
__device__ __align__(16) float g_src_r[RH * RW * SRCP];
__device__ __align__(16) float g_im_r[RH * RW * IMP];
__device__ __align__(16) float g_out_lr[RH * RW * SRCP];

// ---------------------------------------------------------------------------
// Downsample 512 -> 128 (both axes), antialiased triangle kernel, matching
// jax.image.resize(method='bilinear', antialias=True):
//   sample_f = 4*i + 1.5 ; taps j = 4i-2 .. 4i+5 ; w = 1 - |sample_f - j|/4
//   -> tap weights {1,3,5,7,7,5,3,1}/8, renormalized over in-range taps.
// One thread per (low-res pixel, padded channel). Pad channels written as 0.
// ---------------------------------------------------------------------------
__global__ void downsample_kernel(const float* __restrict__ in,
                                  float* __restrict__ out,
                                  int Cin, int Cpad, int total) {
    int idx = blockIdx.x * blockDim.x + threadIdx.x;
    if (idx >= total) return;
    int c = idx % Cpad;
    int p = idx / Cpad;
    int ox = p % RW;
    int oy = p / RW;
    if (c >= Cin) { out[idx] = 0.f; return; }

    const float bw[8] = {0.125f, 0.375f, 0.625f, 0.875f,
                         0.875f, 0.625f, 0.375f, 0.125f};
    int by = 4 * oy - 2;
    int bx = 4 * ox - 2;
    float wy[8], wx[8];
    float sumy = 0.f, sumx = 0.f;
#pragma unroll
    for (int d = 0; d < 8; d++) {
        int iy = by + d;
        wy[d] = (iy >= 0 && iy < H) ? bw[d] : 0.f;
        sumy += wy[d];
        int ix = bx + d;
        wx[d] = (ix >= 0 && ix < W) ? bw[d] : 0.f;
        sumx += wx[d];
    }

    float acc = 0.f;
#pragma unroll 1
    for (int dy = 0; dy < 8; dy++) {
        if (wy[dy] == 0.f) continue;
        const float* rp = in + ((size_t)(by + dy) * W) * Cin + c;
        float rowacc = 0.f;
#pragma unroll
        for (int dx = 0; dx < 8; dx++) {
            if (wx[dx] != 0.f) {
                rowacc += wx[dx] * __ldg(rp + (size_t)(bx + dx) * Cin);
            }
        }
        acc += wy[dy] * rowacc;
    }
    out[idx] = acc / (sumy * sumx);
}

// ---------------------------------------------------------------------------
// Bilateral filter at 128x128 over a 25x25 window.
//   out[y,x,c] = sum_{|dy|,|dx|<=12} exp(-(dy^2+dx^2)/128 - ||im[n]-im[p]||^2/18)
//                * src[y+dy, x+dx, c]      (src zero outside -> skip OOB rows/cols)
// im neighbors use reflect indexing (loaded once into smem halo).
//
// Parallel decomposition (vs round 0): block (16,4,4) = 256 threads.
//  - (tx, ty) pick a column x and a vertical PAIR of output rows (yA, yA+1),
//    so each src float4 load feeds 8 FFMAs (halves L1 traffic).
//  - tz = g in [0,4) splits the 26 source rows of the pair's union window
//    (dyA in [-12, 13]) into 4 interleaved groups -> 4x the warps of round 0.
//  Partial 2x24-channel sums are reduced through shared memory (stride padded
//  48->52 floats to keep STS.128 conflict-free).
// Grid: 8 x 16 = 128 blocks, 8 warps each.
// ---------------------------------------------------------------------------
#define RED_STRIDE 52
__global__ __launch_bounds__(256) void bilateral_kernel() {
    // Union buffer: phase 1 = im halo (32 x 41 float4 = 5248 floats),
    //               phase 2 = reduction scratch (3 * 64 * 52 = 9984 floats).
    __shared__ __align__(16) float sbuf[3 * 64 * RED_STRIDE];
    float4 (*im_sh)[41] = (float4 (*)[41])sbuf;

    const int tx = threadIdx.x;        // 0..15 : column in tile
    const int ty = threadIdx.y;        // 0..3  : row-pair in tile
    const int g  = threadIdx.z;        // 0..3  : window-row group
    const int tid = (g * 4 + ty) * 16 + tx;
    const int x0 = blockIdx.x * 16;
    const int y0 = blockIdx.y * 8;
    const int gy0 = y0 - RAD;
    const int gx0 = x0 - RAD;

    // Fill im halo (rows y0-12 .. y0+19, cols x0-12 .. x0+27) with reflect.
    for (int i = tid; i < 32 * 40; i += 256) {
        int r = i / 40;
        int col = i % 40;
        int gy = gy0 + r;
        if (gy < 0) gy = -gy;
        if (gy > RH - 1) gy = 2 * (RH - 1) - gy;
        int gx = gx0 + col;
        if (gx < 0) gx = -gx;
        if (gx > RW - 1) gx = 2 * (RW - 1) - gx;
        im_sh[r][col] = *(const float4*)(g_im_r + (gy * RW + gx) * IMP);
    }
    __syncthreads();

    const int x = x0 + tx;
    const int yA = y0 + ty * 2;
    const int yB = yA + 1;

    const float4 ca = im_sh[yA - gy0][tx + RAD];
    const float4 cb = im_sh[yB - gy0][tx + RAD];

    float accA[SRCP];
    float accB[SRCP];
#pragma unroll
    for (int q = 0; q < SRCP; q++) { accA[q] = 0.f; accB[q] = 0.f; }

    const float INV128 = 1.0f / 128.0f;   // 1/(2*theta_alpha^2)
    const float INV18  = 1.0f / 18.0f;    // 1/(2*theta_beta^2)

    const float4* src4 = (const float4*)g_src_r;
    const int sxlo = max(x - RAD, 0);
    const int sxhi = min(x + RAD, RW - 1);

    // Union window rows for the pair: dyA in [-12, 13]; group g takes every
    // 4th row starting at g-12. (g=0: dyA=-12..12 [7 rows incl. +12];
    // g=1: -11..13 [7]; g=2: -10..10 [6]; g=3: -9..11 [6].)
#pragma unroll 1
    for (int dyA = g - 12; dyA <= 13; dyA += 4) {
        const int sy = yA + dyA;
        if (sy < 0 || sy >= RH) continue;          // src zero-padded -> skip
        const int dyB = dyA - 1;
        const float sA = (float)(dyA * dyA);
        const float sB = (float)(dyB * dyB);
        const bool vA = (dyA <= RAD);
        const bool vB = (dyB >= -RAD);
        const float4* srow = src4 + sy * RW * 6;
        const float4* imrow = im_sh[sy - gy0];

#pragma unroll 1
        for (int sx = sxlo; sx <= sxhi; ++sx) {
            const int dx = sx - x;
            const float4 cn = imrow[sx - gx0];
            float d0 = cn.x - ca.x, d1 = cn.y - ca.y, d2 = cn.z - ca.z;
            float distA = d0 * d0 + d1 * d1 + d2 * d2;
            float e0 = cn.x - cb.x, e1 = cn.y - cb.y, e2 = cn.z - cb.z;
            float distB = e0 * e0 + e1 * e1 + e2 * e2;
            const float sp = (float)(dx * dx);
            float wA = vA ? __expf(fmaf(-(sA + sp), INV128, -distA * INV18)) : 0.f;
            float wB = vB ? __expf(fmaf(-(sB + sp), INV128, -distB * INV18)) : 0.f;

            const float4* spx = srow + sx * 6;
#pragma unroll
            for (int q = 0; q < 6; q++) {
                float4 s = __ldg(spx + q);
                accA[4 * q + 0] += wA * s.x;
                accA[4 * q + 1] += wA * s.y;
                accA[4 * q + 2] += wA * s.z;
                accA[4 * q + 3] += wA * s.w;
                accB[4 * q + 0] += wB * s.x;
                accB[4 * q + 1] += wB * s.y;
                accB[4 * q + 2] += wB * s.z;
                accB[4 * q + 3] += wB * s.w;
            }
        }
    }

    // Cross-group reduction through shared memory (reusing the halo buffer).
    __syncthreads();   // all im_sh reads done before overwrite
    const int pix = ty * 16 + tx;       // 0..63 pair id
    if (g > 0) {
        float* dst = sbuf + ((g - 1) * 64 + pix) * RED_STRIDE;
#pragma unroll
        for (int q = 0; q < 6; q++) {
            ((float4*)dst)[q] = make_float4(accA[4*q+0], accA[4*q+1],
                                            accA[4*q+2], accA[4*q+3]);
            ((float4*)dst)[6 + q] = make_float4(accB[4*q+0], accB[4*q+1],
                                                accB[4*q+2], accB[4*q+3]);
        }
    }
    __syncthreads();
    if (g == 0) {
#pragma unroll 1
        for (int gg = 0; gg < 3; gg++) {
            const float* s = sbuf + (gg * 64 + pix) * RED_STRIDE;
#pragma unroll
            for (int q = 0; q < SRCP; q++) {
                accA[q] += s[q];
                accB[q] += s[24 + q];
            }
        }
        float4* oA = (float4*)(g_out_lr + (yA * RW + x) * SRCP);
        float4* oB = (float4*)(g_out_lr + (yB * RW + x) * SRCP);
#pragma unroll
        for (int q = 0; q < 6; q++) {
            oA[q] = make_float4(accA[4*q+0], accA[4*q+1], accA[4*q+2], accA[4*q+3]);
            oB[q] = make_float4(accB[4*q+0], accB[4*q+1], accB[4*q+2], accB[4*q+3]);
        }
    }
}

// ---------------------------------------------------------------------------
// Upsample 128 -> 512, matching jax.image.resize bilinear (antialias is a
// no-op when upscaling): pos = 0.25*i - 0.375; edge renormalization == clamp.
// ---------------------------------------------------------------------------
__global__ void upsample_kernel(float* __restrict__ out) {
    int idx = blockIdx.x * blockDim.x + threadIdx.x;
    const int total = H * W * CS;
    if (idx >= total) return;
    int c = idx % CS;
    int p = idx / CS;
    int ox = p % W;
    int oy = p / W;

    float py = 0.25f * oy - 0.375f;
    int jy = (int)floorf(py);
    float fy = py - (float)jy;
    if (jy < 0) { jy = 0; fy = 0.f; }
    if (jy > RH - 2) { jy = RH - 2; fy = 1.f; }

    float px = 0.25f * ox - 0.375f;
    int jx = (int)floorf(px);
    float fx = px - (float)jx;
    if (jx < 0) { jx = 0; fx = 0.f; }
    if (jx > RW - 2) { jx = RW - 2; fx = 1.f; }

    const float* L = g_out_lr;
    size_t b00 = ((size_t)jy * RW + jx) * SRCP + c;
    float v00 = __ldg(L + b00);
    float v01 = __ldg(L + b00 + SRCP);
    float v10 = __ldg(L + b00 + (size_t)RW * SRCP);
    float v11 = __ldg(L + b00 + (size_t)RW * SRCP + SRCP);

    float top = v00 + fx * (v01 - v00);
    float bot = v10 + fx * (v11 - v10);
    out[idx] = top + fy * (bot - top);
}

extern "C" void kernel_launch(void* const* d_in, const int* in_sizes, int n_in,
                              void* d_out, int out_size) {
    const float* src = (const float*)d_in[0];
    const float* im  = (const float*)d_in[1];
    // Defensive: src is the larger input (512*512*21 vs 512*512*3).
    if (n_in >= 2 && in_sizes[0] < in_sizes[1]) {
        src = (const float*)d_in[1];
        im  = (const float*)d_in[0];
    }

    float* p_src_r = nullptr;
    float* p_im_r = nullptr;
    cudaGetSymbolAddress((void**)&p_src_r, g_src_r);
    cudaGetSymbolAddress((void**)&p_im_r, g_im_r);

    {   // downsample src (pad channels to 24)
        int total = RH * RW * SRCP;
        downsample_kernel<<<(total + 255) / 256, 256>>>(src, p_src_r, CS, SRCP, total);
    }
    {   // downsample im (pad channels to 4)
        int total = RH * RW * IMP;
        downsample_kernel<<<(total + 255) / 256, 256>>>(im, p_im_r, CI, IMP, total);
    }
    {   // bilateral at low res
        dim3 b(16, 4, 4);
        dim3 g(RW / 16, RH / 8);
        bilateral_kernel<<<g, b>>>();
    }
    {   // upsample to output
        int total = H * W * CS;
        upsample_kernel<<<(total + 255) / 256, 256>>>((float*)d_out);
    }
}

// round 4
// speedup vs baseline: 1.2138x; 1.2138x over previous
#include <cuda_runtime.h>

#define H 512
#define W 512
#define CS 21          // src channels
#define CI 3           // im channels
#define RH 128
#define RW 128
#define RAD 12
#define SRCP 24        // padded channels (6 x float4)
#define IMP 4          // im padded channels

// Scratch in device globals (no allocation allowed).
__device__ __align__(16) float g_tmp_src[H * RW * SRCP];   // after horizontal pass
__device__ __align__(16) float g_tmp_im [H * RW * IMP];
__device__ __align__(16) float g_src_r[RH * RW * SRCP];
__device__ __align__(16) float g_im_r [RH * RW * IMP];
__device__ __align__(16) float g_out_lr[RH * RW * SRCP];

__device__ __constant__ float c_bw[8] = {0.125f, 0.375f, 0.625f, 0.875f,
                                         0.875f, 0.625f, 0.375f, 0.125f};

// ---------------------------------------------------------------------------
// Separable antialiased 4x downsample, matching jax.image.resize bilinear:
// taps j = 4i-2 .. 4i+5, weights {1,3,5,7,7,5,3,1}/8, per-dim renormalized
// over in-range taps. Horizontal pass stages one full input row in smem
// (coalesced float4 global loads), then computes 128 output cols per row.
// ---------------------------------------------------------------------------
template <int CIN, int CPAD>
__global__ __launch_bounds__(256) void ds_h_kernel(const float* __restrict__ in,
                                                   float* __restrict__ tmp) {
    __shared__ __align__(16) float srow[W * CIN];
    const int y = blockIdx.x;
    const int tid = threadIdx.x;

    // Load the entire input row (W*CIN floats) coalesced as float4.
    const float4* in4 = (const float4*)(in + (size_t)y * W * CIN);
    float4* s4 = (float4*)srow;
    const int n4 = W * CIN / 4;
    for (int i = tid; i < n4; i += 256) s4[i] = in4[i];
    __syncthreads();

    float* orow = tmp + (size_t)y * RW * CPAD;
    for (int o = tid; o < RW * CPAD; o += 256) {
        const int c = o % CPAD;
        const int ox = o / CPAD;
        if (c >= CIN) { orow[o] = 0.f; continue; }
        const int bx = 4 * ox - 2;
        float acc = 0.f, wsum = 0.f;
#pragma unroll
        for (int d = 0; d < 8; d++) {
            const int ix = bx + d;
            if (ix >= 0 && ix < W) {
                acc += c_bw[d] * srow[ix * CIN + c];
                wsum += c_bw[d];
            }
        }
        orow[o] = acc / wsum;
    }
}

// Vertical pass: fully coalesced float4 in and out.
template <int CPAD>
__global__ __launch_bounds__(256) void ds_v_kernel(const float* __restrict__ tmp,
                                                   float* __restrict__ out) {
    const int C4 = CPAD / 4;
    const int total = RH * RW * C4;
    int idx = blockIdx.x * blockDim.x + threadIdx.x;
    if (idx >= total) return;
    const int c4 = idx % C4;
    const int p = idx / C4;
    const int ox = p % RW;
    const int oy = p / RW;
    const int by = 4 * oy - 2;

    const float4* t4 = (const float4*)tmp;
    float ax = 0.f, ay = 0.f, az = 0.f, aw = 0.f, wsum = 0.f;
#pragma unroll
    for (int d = 0; d < 8; d++) {
        const int iy = by + d;
        if (iy >= 0 && iy < H) {
            const float wv = c_bw[d];
            float4 v = t4[(size_t)(iy * RW + ox) * C4 + c4];
            ax += wv * v.x; ay += wv * v.y; az += wv * v.z; aw += wv * v.w;
            wsum += wv;
        }
    }
    const float inv = 1.0f / wsum;
    ((float4*)out)[idx] = make_float4(ax * inv, ay * inv, az * inv, aw * inv);
}

// ---------------------------------------------------------------------------
// Bilateral filter at 128x128 over a 25x25 window.
//   out[y,x,c] = sum_{|dy|,|dx|<=12} exp(-(dy^2+dx^2)/128 - ||im[n]-im[p]||^2/18)
//                * src[y+dy, x+dx, c]      (src zero outside -> skip OOB)
// Block (16,4,8) = 512 threads: (tx,ty) -> column x + output-row PAIR (yA,yA+1)
// so each src float4 feeds 8 FFMAs; tz=g in [0,8) splits the pair's 26 union
// window rows (dyA in [-12,13], stride 8). 16 warps/SM hides exp+L1 latency.
// Cross-group reduction in two smem phases (stride 25 -> conflict-free).
// ---------------------------------------------------------------------------
#define RED_PIX 25
__global__ __launch_bounds__(512) void bilateral_kernel() {
    // Union: phase 1 im halo (32 x 41 float4 = 5248 floats), phase 2 reduction
    // scratch (7 * 64 * 25 = 11200 floats = 44.8KB).
    __shared__ __align__(16) float sbuf[7 * 64 * RED_PIX];
    float4 (*im_sh)[41] = (float4 (*)[41])sbuf;

    const int tx = threadIdx.x;        // 0..15 column
    const int ty = threadIdx.y;        // 0..3  row pair
    const int g  = threadIdx.z;        // 0..7  window-row group
    const int tid = (g * 4 + ty) * 16 + tx;
    const int x0 = blockIdx.x * 16;
    const int y0 = blockIdx.y * 8;
    const int gy0 = y0 - RAD;
    const int gx0 = x0 - RAD;

    // im halo (rows y0-12..y0+19, cols x0-12..x0+27), reflect indexing.
    for (int i = tid; i < 32 * 40; i += 512) {
        int r = i / 40;
        int col = i % 40;
        int gy = gy0 + r;
        if (gy < 0) gy = -gy;
        if (gy > RH - 1) gy = 2 * (RH - 1) - gy;
        int gx = gx0 + col;
        if (gx < 0) gx = -gx;
        if (gx > RW - 1) gx = 2 * (RW - 1) - gx;
        im_sh[r][col] = *(const float4*)(g_im_r + (gy * RW + gx) * IMP);
    }
    __syncthreads();

    const int x = x0 + tx;
    const int yA = y0 + ty * 2;
    const int yB = yA + 1;

    const float4 ca = im_sh[yA - gy0][tx + RAD];
    const float4 cb = im_sh[yB - gy0][tx + RAD];

    float accA[SRCP];
    float accB[SRCP];
#pragma unroll
    for (int q = 0; q < SRCP; q++) { accA[q] = 0.f; accB[q] = 0.f; }

    const float INV128 = 1.0f / 128.0f;   // 1/(2*theta_alpha^2)
    const float INV18  = 1.0f / 18.0f;    // 1/(2*theta_beta^2)

    const float4* src4 = (const float4*)g_src_r;
    const int sxlo = max(x - RAD, 0);
    const int sxhi = min(x + RAD, RW - 1);

#pragma unroll 1
    for (int dyA = g - 12; dyA <= 13; dyA += 8) {
        const int sy = yA + dyA;
        if (sy < 0 || sy >= RH) continue;          // src zero-padded -> skip
        const int dyB = dyA - 1;
        const float sA = (float)(dyA * dyA);
        const float sB = (float)(dyB * dyB);
        const bool vA = (dyA <= RAD);
        const bool vB = (dyB >= -RAD);
        const float4* srow = src4 + sy * RW * 6;
        const float4* imrow = im_sh[sy - gy0];

#pragma unroll 1
        for (int sx = sxlo; sx <= sxhi; ++sx) {
            const int dx = sx - x;
            const float4 cn = imrow[sx - gx0];
            float d0 = cn.x - ca.x, d1 = cn.y - ca.y, d2 = cn.z - ca.z;
            float distA = d0 * d0 + d1 * d1 + d2 * d2;
            float e0 = cn.x - cb.x, e1 = cn.y - cb.y, e2 = cn.z - cb.z;
            float distB = e0 * e0 + e1 * e1 + e2 * e2;
            const float sp = (float)(dx * dx);
            float wA = vA ? __expf(fmaf(-(sA + sp), INV128, -distA * INV18)) : 0.f;
            float wB = vB ? __expf(fmaf(-(sB + sp), INV128, -distB * INV18)) : 0.f;

            const float4* spx = srow + sx * 6;
#pragma unroll
            for (int q = 0; q < 6; q++) {
                float4 s = __ldg(spx + q);
                accA[4 * q + 0] += wA * s.x;
                accA[4 * q + 1] += wA * s.y;
                accA[4 * q + 2] += wA * s.z;
                accA[4 * q + 3] += wA * s.w;
                accB[4 * q + 0] += wB * s.x;
                accB[4 * q + 1] += wB * s.y;
                accB[4 * q + 2] += wB * s.z;
                accB[4 * q + 3] += wB * s.w;
            }
        }
    }

    // Two-phase cross-group reduction (stride 25 -> bank-conflict-free).
    __syncthreads();
    const int pix = ty * 16 + tx;   // 0..63 pair id
    if (g > 0) {
        float* d = sbuf + ((g - 1) * 64 + pix) * RED_PIX;
#pragma unroll
        for (int q = 0; q < SRCP; q++) d[q] = accA[q];
    }
    __syncthreads();
    if (g == 0) {
#pragma unroll 1
        for (int gg = 0; gg < 7; gg++) {
            const float* s = sbuf + (gg * 64 + pix) * RED_PIX;
#pragma unroll
            for (int q = 0; q < SRCP; q++) accA[q] += s[q];
        }
    }
    __syncthreads();
    if (g > 0) {
        float* d = sbuf + ((g - 1) * 64 + pix) * RED_PIX;
#pragma unroll
        for (int q = 0; q < SRCP; q++) d[q] = accB[q];
    }
    __syncthreads();
    if (g == 0) {
#pragma unroll 1
        for (int gg = 0; gg < 7; gg++) {
            const float* s = sbuf + (gg * 64 + pix) * RED_PIX;
#pragma unroll
            for (int q = 0; q < SRCP; q++) accB[q] += s[q];
        }
        float4* oA = (float4*)(g_out_lr + (yA * RW + x) * SRCP);
        float4* oB = (float4*)(g_out_lr + (yB * RW + x) * SRCP);
#pragma unroll
        for (int q = 0; q < 6; q++) {
            oA[q] = make_float4(accA[4*q+0], accA[4*q+1], accA[4*q+2], accA[4*q+3]);
            oB[q] = make_float4(accB[4*q+0], accB[4*q+1], accB[4*q+2], accB[4*q+3]);
        }
    }
}

// ---------------------------------------------------------------------------
// Upsample 128 -> 512 (jax bilinear: pos = 0.25*i - 0.375; edge == clamp).
// 4x in each axis has only 4 (offset,frac) phases:
//   r=0: jy=k-1 f=0.625 | r=1: jy=k-1 f=0.875 | r=2: jy=k f=0.125 | r=3: jy=k f=0.375
// Block = 4 output rows (one y-phase group) x 64 output cols x 21 ch; the
// needed 3x18 low-res pixel patch is staged in smem with clamped indexing
// (clamping makes edge lerp automatically correct: top==bot rows).
// ---------------------------------------------------------------------------
__global__ __launch_bounds__(256) void upsample_kernel(float* __restrict__ out) {
    __shared__ __align__(16) float ls[3 * 18 * SRCP];   // 5.2 KB

    const int xt = blockIdx.x;   // 0..7  : 64-col group
    const int yg = blockIdx.y;   // 0..127: 4-row group
    const int tid = threadIdx.x;

    // Stage 3 x 18 low-res pixels (clamped) as float4.
    const float4* L4 = (const float4*)g_out_lr;
    float4* ls4 = (float4*)ls;
    for (int j = tid; j < 3 * 18 * 6; j += 256) {
        int lr = j / 108;
        int rem = j % 108;
        int lc = rem / 6;
        int c4 = rem % 6;
        int gy = min(max(yg - 1 + lr, 0), RH - 1);
        int gx = min(max(16 * xt - 1 + lc, 0), RW - 1);
        ls4[j] = L4[(size_t)(gy * RW + gx) * 6 + c4];
    }
    __syncthreads();

    const float frac[4] = {0.625f, 0.875f, 0.125f, 0.375f};
    const size_t base = ((size_t)(4 * yg) * W + 64 * xt) * CS;

    // 4 rows x 64 cols x 21 ch = 5376 outputs; 21 per thread; stores coalesced.
    for (int i = tid; i < 4 * 64 * CS; i += 256) {
        const int r = i / (64 * CS);
        const int rem = i % (64 * CS);
        const int oxl = rem / CS;
        const int c = rem % CS;

        const int ry = (r < 2) ? 0 : 1;
        const float fy = frac[r];
        const int xr = oxl & 3;
        const int lx = (oxl >> 2) + ((xr < 2) ? 0 : 1);
        const float fx = frac[xr];

        const float* p00 = ls + (ry * 18 + lx) * SRCP + c;
        const float v00 = p00[0];
        const float v01 = p00[SRCP];
        const float v10 = p00[18 * SRCP];
        const float v11 = p00[18 * SRCP + SRCP];

        const float top = v00 + fx * (v01 - v00);
        const float bot = v10 + fx * (v11 - v10);
        out[base + (size_t)r * (W * CS) + rem] = top + fy * (bot - top);
    }
}

extern "C" void kernel_launch(void* const* d_in, const int* in_sizes, int n_in,
                              void* d_out, int out_size) {
    const float* src = (const float*)d_in[0];
    const float* im  = (const float*)d_in[1];
    if (n_in >= 2 && in_sizes[0] < in_sizes[1]) {   // src is the larger input
        src = (const float*)d_in[1];
        im  = (const float*)d_in[0];
    }

    float *p_tmp_src, *p_tmp_im, *p_src_r, *p_im_r;
    cudaGetSymbolAddress((void**)&p_tmp_src, g_tmp_src);
    cudaGetSymbolAddress((void**)&p_tmp_im,  g_tmp_im);
    cudaGetSymbolAddress((void**)&p_src_r,   g_src_r);
    cudaGetSymbolAddress((void**)&p_im_r,    g_im_r);

    ds_h_kernel<CS, SRCP><<<H, 256>>>(src, p_tmp_src);
    ds_h_kernel<CI, IMP ><<<H, 256>>>(im,  p_tmp_im);
    {
        int total = RH * RW * (SRCP / 4);
        ds_v_kernel<SRCP><<<(total + 255) / 256, 256>>>(p_tmp_src, p_src_r);
    }
    {
        int total = RH * RW * (IMP / 4);
        ds_v_kernel<IMP><<<(total + 255) / 256, 256>>>(p_tmp_im, p_im_r);
    }
    {
        dim3 b(16, 4, 8);
        dim3 g(RW / 16, RH / 8);
        bilateral_kernel<<<g, b>>>();
    }
    {
        dim3 g(8, 128);
        upsample_kernel<<<g, 256>>>((float*)d_out);
    }
}

// round 5
// speedup vs baseline: 1.3539x; 1.1154x over previous
#include <cuda_runtime.h>

#define H 512
#define W 512
#define CS 21          // src channels
#define CI 3           // im channels
#define RH 128
#define RW 128
#define RAD 12
#define SRCP 24        // padded channels (6 x float4)
#define IMP 4          // im padded channels
#define NPIX (RH * RW)

// Scratch in device globals (no allocation allowed).
__device__ __align__(16) float g_tmp_src[H * RW * SRCP];   // after horizontal pass
__device__ __align__(16) float g_tmp_im [H * RW * IMP];
// src at low res, CHANNEL-GROUP-MAJOR: float4 cg in [0,6), then [y][x].
__device__ __align__(16) float g_src_r[6 * NPIX * 4];
__device__ __align__(16) float g_im_r [NPIX * IMP];        // pixel-major
__device__ __align__(16) float g_out_lr[NPIX * SRCP];      // pixel-major

__device__ __constant__ float c_bw[8] = {0.125f, 0.375f, 0.625f, 0.875f,
                                         0.875f, 0.625f, 0.375f, 0.125f};

// ---------------------------------------------------------------------------
// Separable antialiased 4x downsample, matching jax.image.resize bilinear:
// taps j = 4i-2 .. 4i+5, weights {1,3,5,7,7,5,3,1}/8, per-dim renormalized
// over in-range taps. Horizontal pass stages one full input row in smem.
// ---------------------------------------------------------------------------
template <int CIN, int CPAD>
__global__ __launch_bounds__(256) void ds_h_kernel(const float* __restrict__ in,
                                                   float* __restrict__ tmp) {
    __shared__ __align__(16) float srow[W * CIN];
    const int y = blockIdx.x;
    const int tid = threadIdx.x;

    const float4* in4 = (const float4*)(in + (size_t)y * W * CIN);
    float4* s4 = (float4*)srow;
    const int n4 = W * CIN / 4;
    for (int i = tid; i < n4; i += 256) s4[i] = in4[i];
    __syncthreads();

    float* orow = tmp + (size_t)y * RW * CPAD;
    for (int o = tid; o < RW * CPAD; o += 256) {
        const int c = o % CPAD;
        const int ox = o / CPAD;
        if (c >= CIN) { orow[o] = 0.f; continue; }
        const int bx = 4 * ox - 2;
        float acc = 0.f, wsum = 0.f;
#pragma unroll
        for (int d = 0; d < 8; d++) {
            const int ix = bx + d;
            if (ix >= 0 && ix < W) {
                acc += c_bw[d] * srow[ix * CIN + c];
                wsum += c_bw[d];
            }
        }
        orow[o] = acc / wsum;
    }
}

// Vertical pass: coalesced float4 reads; CHMAJOR selects channel-group-major
// output layout (for the bilateral's coalesced loads).
template <int CPAD, bool CHMAJOR>
__global__ __launch_bounds__(256) void ds_v_kernel(const float* __restrict__ tmp,
                                                   float* __restrict__ out) {
    const int C4 = CPAD / 4;
    const int total = RH * RW * C4;
    int idx = blockIdx.x * blockDim.x + threadIdx.x;
    if (idx >= total) return;
    const int c4 = idx % C4;
    const int p = idx / C4;
    const int ox = p % RW;
    const int oy = p / RW;
    const int by = 4 * oy - 2;

    const float4* t4 = (const float4*)tmp;
    float ax = 0.f, ay = 0.f, az = 0.f, aw = 0.f, wsum = 0.f;
#pragma unroll
    for (int d = 0; d < 8; d++) {
        const int iy = by + d;
        if (iy >= 0 && iy < H) {
            const float wv = c_bw[d];
            float4 v = t4[(size_t)(iy * RW + ox) * C4 + c4];
            ax += wv * v.x; ay += wv * v.y; az += wv * v.z; aw += wv * v.w;
            wsum += wv;
        }
    }
    const float inv = 1.0f / wsum;
    const float4 r = make_float4(ax * inv, ay * inv, az * inv, aw * inv);
    if (CHMAJOR) ((float4*)out)[(size_t)c4 * NPIX + p] = r;
    else         ((float4*)out)[idx] = r;
}

// ---------------------------------------------------------------------------
// Bilateral filter at 128x128 over a 25x25 window.
//   out[y,x,c] = sum exp(-(dy^2+dx^2)/128 - ||im[n]-im[p]||^2/18) * src[n,c]
// src is channel-group-major: a warp's lanes (consecutive x) load CONTIGUOUS
// 512B per LDG.128 (4 L1 lines, was 24 with pixel-major). Fixed 25-trip sx
// loop with clamped addresses + masked weights keeps warps convergent.
// Block (16,4,8)=512: (tx,ty)->column + output-row PAIR; g splits the pair's
// 26 union rows (stride 8). Two-phase smem reduction (stride 25, no conflicts).
// ---------------------------------------------------------------------------
#define RED_PIX 25
__global__ __launch_bounds__(512) void bilateral_kernel() {
    __shared__ __align__(16) float sbuf[7 * 64 * RED_PIX];   // 44.8 KB union
    float4 (*im_sh)[41] = (float4 (*)[41])sbuf;

    const int tx = threadIdx.x;        // 0..15 column
    const int ty = threadIdx.y;        // 0..3  row pair
    const int g  = threadIdx.z;        // 0..7  window-row group
    const int tid = (g * 4 + ty) * 16 + tx;
    const int x0 = blockIdx.x * 16;
    const int y0 = blockIdx.y * 8;
    const int gy0 = y0 - RAD;
    const int gx0 = x0 - RAD;

    // im halo (rows y0-12..y0+19, cols x0-12..x0+27), reflect indexing.
    for (int i = tid; i < 32 * 40; i += 512) {
        int r = i / 40;
        int col = i % 40;
        int gy = gy0 + r;
        if (gy < 0) gy = -gy;
        if (gy > RH - 1) gy = 2 * (RH - 1) - gy;
        int gx = gx0 + col;
        if (gx < 0) gx = -gx;
        if (gx > RW - 1) gx = 2 * (RW - 1) - gx;
        im_sh[r][col] = *(const float4*)(g_im_r + (gy * RW + gx) * IMP);
    }
    __syncthreads();

    const int x = x0 + tx;
    const int yA = y0 + ty * 2;
    const int yB = yA + 1;

    const float4 ca = im_sh[yA - gy0][tx + RAD];
    const float4 cb = im_sh[yB - gy0][tx + RAD];

    float accA[SRCP];
    float accB[SRCP];
#pragma unroll
    for (int q = 0; q < SRCP; q++) { accA[q] = 0.f; accB[q] = 0.f; }

    const float INV128 = 1.0f / 128.0f;   // 1/(2*theta_alpha^2)
    const float INV18  = 1.0f / 18.0f;    // 1/(2*theta_beta^2)

    const float4* src4 = (const float4*)g_src_r;

#pragma unroll 1
    for (int dyA = g - 12; dyA <= 13; dyA += 8) {
        const int sy = yA + dyA;
        if (sy < 0 || sy >= RH) continue;          // src zero-padded -> skip
        const int dyB = dyA - 1;
        const float sA = (float)(dyA * dyA);
        const float sB = (float)(dyB * dyB);
        const bool vA = (dyA <= RAD);
        const bool vB = (dyB >= -RAD);
        const float4* srow = src4 + sy * RW;       // + q*NPIX via imm offsets
        const float4* imrow = im_sh[sy - gy0];

#pragma unroll 1
        for (int k = 0; k < 25; ++k) {
            const int sx = x - RAD + k;
            const bool inx = (sx >= 0) && (sx < RW);
            const int sxc = min(max(sx, 0), RW - 1);
            const int dx = k - RAD;
            const float4 cn = imrow[sx - gx0];
            float d0 = cn.x - ca.x, d1 = cn.y - ca.y, d2 = cn.z - ca.z;
            float distA = d0 * d0 + d1 * d1 + d2 * d2;
            float e0 = cn.x - cb.x, e1 = cn.y - cb.y, e2 = cn.z - cb.z;
            float distB = e0 * e0 + e1 * e1 + e2 * e2;
            const float sp = (float)(dx * dx);
            float wA = (vA && inx) ? __expf(fmaf(-(sA + sp), INV128, -distA * INV18)) : 0.f;
            float wB = (vB && inx) ? __expf(fmaf(-(sB + sp), INV128, -distB * INV18)) : 0.f;

            const float4* spx = srow + sxc;        // lanes -> contiguous 512B
#pragma unroll
            for (int q = 0; q < 6; q++) {
                float4 s = __ldg(spx + q * NPIX);
                accA[4 * q + 0] += wA * s.x;
                accA[4 * q + 1] += wA * s.y;
                accA[4 * q + 2] += wA * s.z;
                accA[4 * q + 3] += wA * s.w;
                accB[4 * q + 0] += wB * s.x;
                accB[4 * q + 1] += wB * s.y;
                accB[4 * q + 2] += wB * s.z;
                accB[4 * q + 3] += wB * s.w;
            }
        }
    }

    // Two-phase cross-group reduction (stride 25 -> bank-conflict-free).
    __syncthreads();
    const int pix = ty * 16 + tx;   // 0..63 pair id
    if (g > 0) {
        float* d = sbuf + ((g - 1) * 64 + pix) * RED_PIX;
#pragma unroll
        for (int q = 0; q < SRCP; q++) d[q] = accA[q];
    }
    __syncthreads();
    if (g == 0) {
#pragma unroll 1
        for (int gg = 0; gg < 7; gg++) {
            const float* s = sbuf + (gg * 64 + pix) * RED_PIX;
#pragma unroll
            for (int q = 0; q < SRCP; q++) accA[q] += s[q];
        }
    }
    __syncthreads();
    if (g > 0) {
        float* d = sbuf + ((g - 1) * 64 + pix) * RED_PIX;
#pragma unroll
        for (int q = 0; q < SRCP; q++) d[q] = accB[q];
    }
    __syncthreads();
    if (g == 0) {
#pragma unroll 1
        for (int gg = 0; gg < 7; gg++) {
            const float* s = sbuf + (gg * 64 + pix) * RED_PIX;
#pragma unroll
            for (int q = 0; q < SRCP; q++) accB[q] += s[q];
        }
        float4* oA = (float4*)(g_out_lr + (yA * RW + x) * SRCP);
        float4* oB = (float4*)(g_out_lr + (yB * RW + x) * SRCP);
#pragma unroll
        for (int q = 0; q < 6; q++) {
            oA[q] = make_float4(accA[4*q+0], accA[4*q+1], accA[4*q+2], accA[4*q+3]);
            oB[q] = make_float4(accB[4*q+0], accB[4*q+1], accB[4*q+2], accB[4*q+3]);
        }
    }
}

// ---------------------------------------------------------------------------
// Upsample 128 -> 512 (jax bilinear: pos = 0.25*i - 0.375; edge == clamp).
// Per-axis 4 phases: jy in {k-1,k-1,k,k}, fy in {.625,.875,.125,.375}.
// Block stages its clamped 3x18 low-res patch in smem.
// ---------------------------------------------------------------------------
__global__ __launch_bounds__(256) void upsample_kernel(float* __restrict__ out) {
    __shared__ __align__(16) float ls[3 * 18 * SRCP];   // 5.2 KB

    const int xt = blockIdx.x;   // 0..7  : 64-col group
    const int yg = blockIdx.y;   // 0..127: 4-row group
    const int tid = threadIdx.x;

    const float4* L4 = (const float4*)g_out_lr;
    float4* ls4 = (float4*)ls;
    for (int j = tid; j < 3 * 18 * 6; j += 256) {
        int lr = j / 108;
        int rem = j % 108;
        int lc = rem / 6;
        int c4 = rem % 6;
        int gy = min(max(yg - 1 + lr, 0), RH - 1);
        int gx = min(max(16 * xt - 1 + lc, 0), RW - 1);
        ls4[j] = L4[(size_t)(gy * RW + gx) * 6 + c4];
    }
    __syncthreads();

    const float frac[4] = {0.625f, 0.875f, 0.125f, 0.375f};
    const size_t base = ((size_t)(4 * yg) * W + 64 * xt) * CS;

    for (int i = tid; i < 4 * 64 * CS; i += 256) {
        const int r = i / (64 * CS);
        const int rem = i % (64 * CS);
        const int oxl = rem / CS;
        const int c = rem % CS;

        const int ry = (r < 2) ? 0 : 1;
        const float fy = frac[r];
        const int xr = oxl & 3;
        const int lx = (oxl >> 2) + ((xr < 2) ? 0 : 1);
        const float fx = frac[xr];

        const float* p00 = ls + (ry * 18 + lx) * SRCP + c;
        const float v00 = p00[0];
        const float v01 = p00[SRCP];
        const float v10 = p00[18 * SRCP];
        const float v11 = p00[18 * SRCP + SRCP];

        const float top = v00 + fx * (v01 - v00);
        const float bot = v10 + fx * (v11 - v10);
        out[base + (size_t)r * (W * CS) + rem] = top + fy * (bot - top);
    }
}

extern "C" void kernel_launch(void* const* d_in, const int* in_sizes, int n_in,
                              void* d_out, int out_size) {
    const float* src = (const float*)d_in[0];
    const float* im  = (const float*)d_in[1];
    if (n_in >= 2 && in_sizes[0] < in_sizes[1]) {   // src is the larger input
        src = (const float*)d_in[1];
        im  = (const float*)d_in[0];
    }

    float *p_tmp_src, *p_tmp_im, *p_src_r, *p_im_r;
    cudaGetSymbolAddress((void**)&p_tmp_src, g_tmp_src);
    cudaGetSymbolAddress((void**)&p_tmp_im,  g_tmp_im);
    cudaGetSymbolAddress((void**)&p_src_r,   g_src_r);
    cudaGetSymbolAddress((void**)&p_im_r,    g_im_r);

    ds_h_kernel<CS, SRCP><<<H, 256>>>(src, p_tmp_src);
    ds_h_kernel<CI, IMP ><<<H, 256>>>(im,  p_tmp_im);
    {
        int total = RH * RW * (SRCP / 4);
        ds_v_kernel<SRCP, true><<<(total + 255) / 256, 256>>>(p_tmp_src, p_src_r);
    }
    {
        int total = RH * RW * (IMP / 4);
        ds_v_kernel<IMP, false><<<(total + 255) / 256, 256>>>(p_tmp_im, p_im_r);
    }
    {
        dim3 b(16, 4, 8);
        dim3 g(RW / 16, RH / 8);
        bilateral_kernel<<<g, b>>>();
    }
    {
        dim3 g(8, 128);
        upsample_kernel<<<g, 256>>>((float*)d_out);
    }
}